// round 11
// baseline (speedup 1.0000x reference)
#include <cuda_runtime.h>

// x[64, 64, 64, 128] fp32.
//   out1 = FWHT along axis 1 (i), element stride 8192
//   out2 = FWHT along axis 2 (j) of out1, element stride 128
// d_out = [out1 | out2].
//
// Chunked dual-stream pipeline, expressed as graph dependencies (no spinlocks,
// no fences): 4 chunks of 16 batches.
//   Stream A: A_c = FWHT_i of chunk c (x -> out1), serialized A0..A3.
//   Stream B: B_c = FWHT_j of chunk c (out1 -> out2), waits only on A_c.
// B_c runs concurrently with A_{c+1}; out1 chunk (32 MB) is still dirty in L2
// (126 MB) when B_c reads it -> out1 re-read is an L2 hit, out1 reaches DRAM
// only via lazy writeback. Effective DRAM traffic ~384 MB vs 512 MB.
// Store drain is fully asynchronous (no threadfence on the critical path).

#define THREADS 256
#define NB 64
#define CB 16                              // batches per chunk
#define NCHUNK (NB / CB)                   // 4
#define COLS_PER_CHUNK (CB * 8192u)        // 131072
#define GRID_C (COLS_PER_CHUNK / THREADS)  // 512 blocks per chunk kernel

__device__ __forceinline__ void butterfly64(float v[64])
{
#pragma unroll
    for (int h = 1; h < 64; h <<= 1)
#pragma unroll
        for (int s = 0; s < 64; s += 2 * h)
#pragma unroll
            for (int k = 0; k < h; k++) {
                float a = v[s + k], b = v[s + k + h];
                v[s + k]     = a + b;
                v[s + k + h] = a - b;
            }
}

template <int STRIDE, bool STREAMOUT>
__global__ __launch_bounds__(THREADS)
void fwht_chunk(const float* __restrict__ in, float* __restrict__ out)
{
    // chunk-local column id; transform stays within a batch, so chunk base
    // offsetting via the pointer is safe for both strides.
    const unsigned g   = blockIdx.x * THREADS + threadIdx.x;
    const size_t base  = (size_t)(g / STRIDE) * (64u * STRIDE) + (g % STRIDE);

    float v[64];
#pragma unroll
    for (int k = 0; k < 64; k++)
        v[k] = __ldcs(in + base + (size_t)k * STRIDE);   // use-once / evict-after

    butterfly64(v);

    if (STREAMOUT) {
#pragma unroll
        for (int k = 0; k < 64; k++)
            __stcs(out + base + (size_t)k * STRIDE, v[k]);   // out2: use-once
    } else {
#pragma unroll
        for (int k = 0; k < 64; k++)
            out[base + (size_t)k * STRIDE] = v[k];           // out1: keep in L2
    }
}

extern "C" void kernel_launch(void* const* d_in, const int* in_sizes, int n_in,
                              void* d_out, int out_size)
{
    const float* x = (const float*)d_in[0];
    float* out1 = (float*)d_out;
    float* out2 = out1 + (size_t)64 * 64 * 64 * 128;

    // Lazily-created side streams/events (resource init only; the GPU work
    // enqueued per call is identical every call).
    static cudaStream_t sA = nullptr, sB = nullptr;
    static cudaEvent_t evFork = nullptr, evJoin = nullptr, evA[NCHUNK];
    if (sA == nullptr) {
        cudaStreamCreateWithFlags(&sA, cudaStreamNonBlocking);
        cudaStreamCreateWithFlags(&sB, cudaStreamNonBlocking);
        cudaEventCreateWithFlags(&evFork, cudaEventDisableTiming);
        cudaEventCreateWithFlags(&evJoin, cudaEventDisableTiming);
        for (int c = 0; c < NCHUNK; c++)
            cudaEventCreateWithFlags(&evA[c], cudaEventDisableTiming);
    }

    const size_t chunk_elems = (size_t)CB * 64 * 8192;   // per-chunk elements

    // fork from the legacy (capture-origin) stream
    cudaEventRecord(evFork, 0);
    cudaStreamWaitEvent(sA, evFork, 0);
    cudaStreamWaitEvent(sB, evFork, 0);

    for (int c = 0; c < NCHUNK; c++) {
        const size_t off = (size_t)c * chunk_elems;
        // pass 1 (chunk c) on stream A
        fwht_chunk<8192, false><<<GRID_C, THREADS, 0, sA>>>(x + off, out1 + off);
        cudaEventRecord(evA[c], sA);
        // pass 2 (chunk c) on stream B, gated only on A_c
        cudaStreamWaitEvent(sB, evA[c], 0);
        fwht_chunk<128, true><<<GRID_C, THREADS, 0, sB>>>(out1 + off, out2 + off);
    }

    // join back to the legacy stream (B3 transitively covers everything)
    cudaEventRecord(evJoin, sB);
    cudaStreamWaitEvent(0, evJoin, 0);
}

// round 12
// speedup vs baseline: 1.0503x; 1.0503x over previous
#include <cuda_runtime.h>

// x[64, 64, 64, 128] fp32.
//   out1 = FWHT along axis 1 (i), element stride 8192
//   out2 = FWHT along axis 2 (j) of out1, element stride 128
// d_out = [out1 | out2].
//
// Round-10 lag pipeline (out1 re-read served from L2; ~344 MB DRAM traffic)
// with the 64-point transform SPLIT ACROSS A LANE PAIR:
//   thread (col, half) holds elements [32*half, 32*half+32) of its column in
//   v[32]. FWHT stages commute, so the cross-half stage (h=32) runs first as
//   one __shfl_xor(1) + FFMA per element; the 5 remaining stages are local.
// Registers drop ~80 -> ~48  =>  4-5 blocks/SM instead of 3, and per-thread
// phases are half as long -> memory and compute interleave across ~2x more
// warps, raising DRAM busy% (the round-10 limiter at 59.8%).

#define THREADS 256
#define NB 64
#define BPB 64                        // blocks per batch-pass (8192 cols * 2 thr / 256)
#define LAG 3
#define GRID ((NB + LAG) * BPB)       // 4288

__device__ int g_cnt1[NB];
__device__ int g_cnt2[NB];

__device__ __forceinline__ void butterfly32(float v[32])
{
#pragma unroll
    for (int h = 1; h < 32; h <<= 1)
#pragma unroll
        for (int s = 0; s < 32; s += 2 * h)
#pragma unroll
            for (int k = 0; k < h; k++) {
                float a = v[s + k], b = v[s + k + h];
                v[s + k]     = a + b;
                v[s + k + h] = a - b;
            }
}

// cross-half stage (h=32): partner is lane^1.
// half 0 computes a+b, half 1 computes a-b, where a = half0 value, b = half1.
__device__ __forceinline__ void cross_stage(float v[32], float s /* +1 or -1 */)
{
#pragma unroll
    for (int k = 0; k < 32; k++) {
        float o = __shfl_xor_sync(0xFFFFFFFFu, v[k], 1);
        v[k] = fmaf(s, v[k], o);      // half0: v+o ; half1: o-v
    }
}

__global__ __launch_bounds__(THREADS)
void wht2_lag2(const float* __restrict__ x,
               float* __restrict__ out1,
               float* __restrict__ out2)
{
    const int grp  = blockIdx.x / BPB;            // 0 .. NB+LAG-1
    const int sub  = blockIdx.x % BPB;
    const int t    = threadIdx.x;
    const int half = t & 1;
    const float sgn = half ? -1.0f : 1.0f;
    const unsigned col = (unsigned)sub * (THREADS / 2) + (t >> 1);   // 0..8191

    float v[32];

    // ---------------- pass 1: out1[grp] = FWHT_i(x[grp]) ----------------
    if (grp < NB) {
        const size_t bbase = (size_t)grp * (64u * 8192u);
        // col = (j,c); this thread covers i in [32*half, 32*half+32)
        const float* px = x + bbase + col + (size_t)half * 32 * 8192;
#pragma unroll
        for (int k = 0; k < 32; k++)
            v[k] = __ldcs(px + (size_t)k * 8192);

        cross_stage(v, sgn);
        butterfly32(v);

        float* po = out1 + bbase + col + (size_t)half * 32 * 8192;
#pragma unroll
        for (int k = 0; k < 32; k++)
            po[(size_t)k * 8192] = v[k];          // keep in L2 for pass 2

        __threadfence();
        __syncthreads();
        if (t == 0) atomicAdd(&g_cnt1[grp], 1);
    }

    // ---------------- pass 2: out2[m] = FWHT_j(out1[m]), m = grp-LAG ----------------
    if (grp >= LAG) {
        const int m = grp - LAG;

        if (t == 0) {
            while (*(volatile int*)&g_cnt1[m] < BPB)
                __nanosleep(32);
        }
        __syncthreads();
        __threadfence();

        const size_t mbase = (size_t)m * (64u * 8192u);
        // col = (i,c); this thread covers j in [32*half, 32*half+32)
        const size_t base = mbase + (size_t)(col >> 7) * 8192u + (col & 127u)
                          + (size_t)half * 32 * 128;
        const float* pi = out1 + base;
#pragma unroll
        for (int k = 0; k < 32; k++)
            v[k] = __ldcs(pi + (size_t)k * 128);  // L2-hot

        cross_stage(v, sgn);
        butterfly32(v);

        float* po = out2 + base;
#pragma unroll
        for (int k = 0; k < 32; k++)
            __stcs(po + (size_t)k * 128, v[k]);   // use-once write

        // self-reset counters for next graph replay
        __syncthreads();
        if (t == 0) {
            int done = atomicAdd(&g_cnt2[m], 1) + 1;
            if (done == BPB) {
                atomicExch(&g_cnt2[m], 0);
                atomicExch(&g_cnt1[m], 0);
            }
        }
    }
}

extern "C" void kernel_launch(void* const* d_in, const int* in_sizes, int n_in,
                              void* d_out, int out_size)
{
    const float* x = (const float*)d_in[0];
    float* out1 = (float*)d_out;
    float* out2 = out1 + (size_t)64 * 64 * 64 * 128;

    wht2_lag2<<<GRID, THREADS>>>(x, out1, out2);
}